// round 15
// baseline (speedup 1.0000x reference)
#include <cuda_runtime.h>
#include <cuda_fp16.h>
#include <math.h>
#include <stdint.h>
#include <mma.h>

using namespace nvcuda;

// ---------------- problem constants ----------------
#define D_DIM   1024
#define F_DIM   704
#define E_NUM   64
#define NTOK    1024
#define TOPK    6
#define FS_DIM  1408
#define NPAIR   (NTOK*TOPK)

// ---------------- scratch (static device arrays) ----------------
__device__ __half g_hbuf[NPAIR * F_DIM];
__device__ float  g_dbuf[NPAIR * D_DIM];
__device__ __half g_sh[NTOK * FS_DIM];
__device__ int    g_count[E_NUM];
__device__ int    g_offset[E_NUM];
__device__ int    g_cursor[E_NUM];
__device__ int    g_tok_expert[NTOK*TOPK];
__device__ float  g_tok_w[NTOK*TOPK];
__device__ int    g_tok_pair[NTOK*TOPK];
__device__ int    g_pair_token[NPAIR];
__device__ float  g_pair_w[NPAIR];
__device__ float  g_scores_scratch[NTOK * E_NUM];

// ---------------- smem geometry ----------------
#define LDA_H 40     // halfs per A row (32 + 8 pad)
#define LDB_H 72     // halfs per B row (64 + 8 pad)
#define LDC   68     // floats per C row
#define NSTAGE 4
// up stage (halfs): A 128*40=5120 @0, B1 32*72=2304 @5120, B2 @7424 -> 9728
#define STG_UP_H 9728
#define TOK_OFF_B (NSTAGE*STG_UP_H*2)            // 77824
#define MB_UP_OFF (TOK_OFF_B + 512)              // 78336
#define SMEM_UP_B (MB_UP_OFF + 64)               // 78400
// down stage (halfs): A 5120 + B 2304 = 7424
#define STG_DN_H 7424
#define MB_DN_OFF (NSTAGE*STG_DN_H*2)            // 59392
#define SMEM_DN_B (MB_DN_OFF + 64)               // 59456

// ---------------- mbarrier helpers (sm_90-level PTX, compiles on sm_103) ----
__device__ __forceinline__ void mbar_init(uint32_t a, uint32_t n) {
    asm volatile("mbarrier.init.shared.b64 [%0], %1;" :: "r"(a), "r"(n) : "memory");
}
__device__ __forceinline__ void mbar_arrive(uint32_t a) {
    asm volatile("{ .reg .b64 t; mbarrier.arrive.shared.b64 t, [%0]; }"
                 :: "r"(a) : "memory");
}
__device__ __forceinline__ void mbar_wait(uint32_t a, uint32_t ph) {
    asm volatile(
        "{\n\t.reg .pred P;\n\t"
        "WL_%=:\n\t"
        "mbarrier.try_wait.parity.acquire.cta.shared::cta.b64 P, [%0], %1, 0x989680;\n\t"
        "@P bra WD_%=;\n\t"
        "bra WL_%=;\n\t"
        "WD_%=:\n\t}"
        :: "r"(a), "r"(ph) : "memory");
}

// ---------------- WMMA fp16 ----------------
using FragA = wmma::fragment<wmma::matrix_a, 16, 16, 16, __half, wmma::row_major>;
using FragB = wmma::fragment<wmma::matrix_b, 16, 16, 16, __half, wmma::row_major>;
using FragC = wmma::fragment<wmma::accumulator, 16, 16, 16, float>;

__device__ __forceinline__ void sts_f4_h4(__half* dst, float4 v) {
    __half2 p0 = __floats2half2_rn(v.x, v.y);
    __half2 p1 = __floats2half2_rn(v.z, v.w);
    uint2 u = make_uint2(*(uint32_t*)&p0, *(uint32_t*)&p1);
    *(uint2*)dst = u;
}

// ---------------- small kernels ----------------
__global__ void init_kernel() {
    int i = threadIdx.x;
    if (i < E_NUM) { g_count[i] = 0; g_cursor[i] = 0; }
}

__global__ void gate_kernel(const float* __restrict__ x,
                            const float* __restrict__ wg,
                            const float* __restrict__ gb,
                            float* __restrict__ scores_out) {
    __shared__ float xs[D_DIM];
    __shared__ float sc[E_NUM];
    int t = blockIdx.x;
    int tid = threadIdx.x;

    const float4* xv = (const float4*)(x + (size_t)t * D_DIM);
    float4* xsv = (float4*)xs;
    for (int i = tid; i < D_DIM/4; i += 128) xsv[i] = xv[i];
    __syncthreads();

    if (tid < E_NUM) {
        const float4* wv = (const float4*)(wg + (size_t)tid * D_DIM);
        float acc = 0.f;
        #pragma unroll 8
        for (int i = 0; i < D_DIM/4; i++) {
            float4 a = xsv[i]; float4 b = wv[i];
            acc += a.x*b.x + a.y*b.y + a.z*b.z + a.w*b.w;
        }
        float s = 1.f/(1.f + expf(-acc)) + gb[tid];
        sc[tid] = s;
        scores_out[(size_t)t * E_NUM + tid] = s;
    }
    __syncthreads();

    if (tid == 0) {
        float tmp[E_NUM];
        for (int i = 0; i < E_NUM; i++) tmp[i] = sc[i];
        int   sel[TOPK]; float selw[TOPK];
        float wsum = 0.f;
        for (int k = 0; k < TOPK; k++) {
            int bi = 0; float bv = tmp[0];
            for (int i = 1; i < E_NUM; i++)
                if (tmp[i] > bv) { bv = tmp[i]; bi = i; }
            sel[k] = bi; selw[k] = bv; wsum += bv;
            tmp[bi] = -1e30f;
        }
        float inv = 1.f / wsum;
        for (int k = 0; k < TOPK; k++) {
            int e = sel[k];
            g_tok_expert[t*TOPK + k] = e;
            g_tok_w[t*TOPK + k] = selw[k] * inv;
            atomicAdd(&g_count[e], 1);
        }
    }
}

__global__ void scan_assign_kernel() {
    if (threadIdx.x == 0) {
        int acc = 0;
        for (int e = 0; e < E_NUM; e++) { g_offset[e] = acc; acc += g_count[e]; }
    }
    __syncthreads();
    int t = threadIdx.x;
    #pragma unroll
    for (int k = 0; k < TOPK; k++) {
        int e = g_tok_expert[t*TOPK + k];
        int slot = atomicAdd(&g_cursor[e], 1);
        int p = g_offset[e] + slot;
        g_pair_token[p] = t;
        g_pair_w[p] = g_tok_w[t*TOPK + k];
        g_tok_pair[t*TOPK + k] = p;
    }
}

// ===========================================================================
// Fused up-proj (fp16 MMA, warp-specialized): routed (y<64) + shared (y==64).
// 512 threads: warps 0-7 consumers (4x2, 32x32 tiles), warps 8-15 producers.
// 4-stage smem ring with full/empty mbarriers. grid (22, 65, 8).
// ===========================================================================
__global__ void __launch_bounds__(512, 1)
up_fused(const float* __restrict__ x,
         const float* __restrict__ w1r,
         const float* __restrict__ w3r,
         const float* __restrict__ w1s,
         const float* __restrict__ w3s) {
    extern __shared__ __half smh[];
    const int tid = threadIdx.x;
    const int y = blockIdx.y;
    const bool se = (y == E_NUM);
    const int f0 = blockIdx.x * 64;
    const int row0 = blockIdx.z * 128;

    int cnt, base, ldB, ldD;
    const float *B1, *B2;
    __half* dstbuf;
    if (se) {
        cnt = NTOK; base = 0;
        B1 = w1s; B2 = w3s; ldB = FS_DIM;
        dstbuf = g_sh; ldD = FS_DIM;
    } else {
        if (f0 >= F_DIM) return;
        cnt = g_count[y];
        if (row0 >= cnt) return;
        base = g_offset[y];
        B1 = w1r + (size_t)y * D_DIM * F_DIM;
        B2 = w3r + (size_t)y * D_DIM * F_DIM;
        ldB = F_DIM;
        dstbuf = g_hbuf; ldD = F_DIM;
    }

    const uint32_t sbase = (uint32_t)__cvta_generic_to_shared(smh);
    const uint32_t mb_full = sbase + MB_UP_OFF;        // 4 x 8B
    const uint32_t mb_empty = sbase + MB_UP_OFF + 32;  // 4 x 8B
    int* toks = (int*)((char*)smh + TOK_OFF_B);

    if (tid < 128) {
        int r = row0 + tid;
        if (se) toks[tid] = r;
        else    toks[tid] = (r < cnt) ? g_pair_token[base + r] : 0;
    }
    if (tid == 0) {
        #pragma unroll
        for (int s = 0; s < NSTAGE; s++) {
            mbar_init(mb_full + s*8, 8);   // 8 producer warps arrive
            mbar_init(mb_empty + s*8, 8);  // 8 consumer warps arrive
        }
    }
    __syncthreads();

    const int wid = tid >> 5;
    const int lane = tid & 31;
    const int nchunk = D_DIM / 32;

    FragC c1[2][2], c3[2][2];
    #pragma unroll
    for (int mi = 0; mi < 2; mi++)
        #pragma unroll
        for (int ni = 0; ni < 2; ni++) {
            wmma::fill_fragment(c1[mi][ni], 0.f);
            wmma::fill_fragment(c3[mi][ni], 0.f);
        }

    const int warpM = (wid & 7) >> 1, warpN = wid & 1;

    if (wid >= 8) {
        // ------------- PRODUCER -------------
        const int ptid = tid - 256;
        const int c4a = ptid & 7;          // A float4 column
        const int arow = ptid >> 3;        // A base row (4 rows, +32)
        const int bc4 = ptid & 15;         // B float4 column
        const int brow = ptid >> 4;        // B base row (2 rows, +16)

        const float4* ar[4];
        #pragma unroll
        for (int i = 0; i < 4; i++)
            ar[i] = (const float4*)(x + (size_t)toks[arow + i*32] * D_DIM);

        int ps = 0, pph = 1;
        for (int kc = 0; kc < nchunk; kc++) {
            mbar_wait(mb_empty + ps*8, pph);
            float4 ra[4], rb1[2], rb3[2];
            #pragma unroll
            for (int i = 0; i < 4; i++) ra[i] = ar[i][kc*8 + c4a];
            #pragma unroll
            for (int i = 0; i < 2; i++) {
                rb1[i] = *(const float4*)(B1 + (size_t)(kc*32 + brow + i*16) * ldB + f0 + bc4*4);
                rb3[i] = *(const float4*)(B2 + (size_t)(kc*32 + brow + i*16) * ldB + f0 + bc4*4);
            }
            __half* St = smh + ps * STG_UP_H;
            #pragma unroll
            for (int i = 0; i < 4; i++)
                sts_f4_h4(St + (arow + i*32) * LDA_H + c4a*4, ra[i]);
            #pragma unroll
            for (int i = 0; i < 2; i++) {
                sts_f4_h4(St + 5120 + (brow + i*16) * LDB_H + bc4*4, rb1[i]);
                sts_f4_h4(St + 7424 + (brow + i*16) * LDB_H + bc4*4, rb3[i]);
            }
            __syncwarp();
            if (lane == 0) mbar_arrive(mb_full + ps*8);
            if (++ps == NSTAGE) { ps = 0; pph ^= 1; }
        }
    } else {
        // ------------- CONSUMER -------------
        int cs = 0, cph = 0;
        for (int kc = 0; kc < nchunk; kc++) {
            mbar_wait(mb_full + cs*8, cph);
            const __half* St  = smh + cs * STG_UP_H;
            const __half* As  = St;
            const __half* B1s = St + 5120;
            const __half* B2s = St + 7424;
            #pragma unroll
            for (int ks = 0; ks < 2; ks++) {
                FragA a[2];
                #pragma unroll
                for (int mi = 0; mi < 2; mi++)
                    wmma::load_matrix_sync(a[mi], As + (warpM*32 + mi*16) * LDA_H + ks*16, LDA_H);
                FragB b;
                #pragma unroll
                for (int ni = 0; ni < 2; ni++) {
                    wmma::load_matrix_sync(b, B1s + (ks*16) * LDB_H + warpN*32 + ni*16, LDB_H);
                    #pragma unroll
                    for (int mi = 0; mi < 2; mi++)
                        wmma::mma_sync(c1[mi][ni], a[mi], b, c1[mi][ni]);
                    wmma::load_matrix_sync(b, B2s + (ks*16) * LDB_H + warpN*32 + ni*16, LDB_H);
                    #pragma unroll
                    for (int mi = 0; mi < 2; mi++)
                        wmma::mma_sync(c3[mi][ni], a[mi], b, c3[mi][ni]);
                }
            }
            __syncwarp();
            if (lane == 0) mbar_arrive(mb_empty + cs*8);
            if (++cs == NSTAGE) { cs = 0; cph ^= 1; }
        }
    }
    __syncthreads();   // all MMAs + last STS done before C tile reuses ring smem

    float* Cs = (float*)smh;
    if (wid < 8) {
        #pragma unroll
        for (int mi = 0; mi < 2; mi++)
            #pragma unroll
            for (int ni = 0; ni < 2; ni++) {
                #pragma unroll
                for (int k = 0; k < c1[mi][ni].num_elements; k++) {
                    float v1 = c1[mi][ni].x[k], v3 = c3[mi][ni].x[k];
                    c1[mi][ni].x[k] = v1 / (1.f + expf(-v1)) * v3;
                }
                wmma::store_matrix_sync(Cs + (warpM*32 + mi*16) * LDC + warpN*32 + ni*16,
                                        c1[mi][ni], LDC, wmma::mem_row_major);
            }
    }
    __syncthreads();

    int valid = cnt - row0; if (valid > 128) valid = 128;
    #pragma unroll
    for (int i = 0; i < 4; i++) {
        int lin = tid + i * 512;
        int row = lin >> 4, cc = lin & 15;
        if (row < valid) {
            float4 v = *(float4*)(Cs + row * LDC + cc * 4);
            __half2 p0 = __floats2half2_rn(v.x, v.y);
            __half2 p1 = __floats2half2_rn(v.z, v.w);
            uint2 u = make_uint2(*(uint32_t*)&p0, *(uint32_t*)&p1);
            *(uint2*)(dstbuf + (size_t)(base + row0 + row) * ldD + f0 + cc * 4) = u;
        }
    }
}

// ===========================================================================
// Fused down-proj (fp16 MMA, warp-specialized): routed (A=g_hbuf, dst=g_dbuf)
//                                               shared (A=g_sh, dst=out).
// 512 threads: 8 consumer + 8 producer warps, 4-stage ring. grid (16, 65, 8).
// ===========================================================================
__global__ void __launch_bounds__(512, 1)
down_fused(const float* __restrict__ w2r,
           const float* __restrict__ w2s,
           float* __restrict__ out) {
    extern __shared__ __half smh[];
    const int tid = threadIdx.x;
    const int y = blockIdx.y;
    const bool se = (y == E_NUM);
    const int d0 = blockIdx.x * 64;
    const int row0 = blockIdx.z * 128;

    int cnt, base, nchunk;
    const float* B1;
    const __half* Abase;
    int ldA;
    float* dstbuf;
    if (se) {
        cnt = NTOK; base = 0;
        B1 = w2s; nchunk = FS_DIM / 32;
        Abase = g_sh; ldA = FS_DIM;
        dstbuf = out;
    } else {
        cnt = g_count[y];
        if (row0 >= cnt) return;
        base = g_offset[y];
        B1 = w2r + (size_t)y * F_DIM * D_DIM;
        nchunk = F_DIM / 32;
        Abase = g_hbuf; ldA = F_DIM;
        dstbuf = g_dbuf;
    }

    const uint32_t sbase = (uint32_t)__cvta_generic_to_shared(smh);
    const uint32_t mb_full = sbase + MB_DN_OFF;
    const uint32_t mb_empty = sbase + MB_DN_OFF + 32;

    if (tid == 0) {
        #pragma unroll
        for (int s = 0; s < NSTAGE; s++) {
            mbar_init(mb_full + s*8, 8);
            mbar_init(mb_empty + s*8, 8);
        }
    }
    __syncthreads();

    const int wid = tid >> 5;
    const int lane = tid & 31;
    const int warpM = (wid & 7) >> 1, warpN = wid & 1;

    FragC c[2][2];
    #pragma unroll
    for (int mi = 0; mi < 2; mi++)
        #pragma unroll
        for (int ni = 0; ni < 2; ni++)
            wmma::fill_fragment(c[mi][ni], 0.f);

    if (wid >= 8) {
        // ------------- PRODUCER -------------
        const int ptid = tid - 256;
        const int c16 = ptid & 3;          // A uint4 column
        const int arow4 = ptid >> 2;       // A rows arow4, arow4+64
        const int bc4 = ptid & 15;
        const int brow = ptid >> 4;

        const uint4* arh[2];
        #pragma unroll
        for (int i = 0; i < 2; i++) {
            int r = row0 + arow4 + i*64;
            int rr = (r < cnt) ? r : (cnt - 1);
            arh[i] = (const uint4*)(Abase + (size_t)(base + rr) * ldA);
        }

        int ps = 0, pph = 1;
        for (int kc = 0; kc < nchunk; kc++) {
            mbar_wait(mb_empty + ps*8, pph);
            uint4 rA[2]; float4 rB[2];
            #pragma unroll
            for (int i = 0; i < 2; i++) rA[i] = arh[i][kc*4 + c16];
            #pragma unroll
            for (int i = 0; i < 2; i++)
                rB[i] = *(const float4*)(B1 + (size_t)(kc*32 + brow + i*16) * D_DIM + d0 + bc4*4);
            __half* St = smh + ps * STG_DN_H;
            #pragma unroll
            for (int i = 0; i < 2; i++)
                *(uint4*)(St + (arow4 + i*64) * LDA_H + c16*8) = rA[i];
            #pragma unroll
            for (int i = 0; i < 2; i++)
                sts_f4_h4(St + 5120 + (brow + i*16) * LDB_H + bc4*4, rB[i]);
            __syncwarp();
            if (lane == 0) mbar_arrive(mb_full + ps*8);
            if (++ps == NSTAGE) { ps = 0; pph ^= 1; }
        }
    } else {
        // ------------- CONSUMER -------------
        int cs = 0, cph = 0;
        for (int kc = 0; kc < nchunk; kc++) {
            mbar_wait(mb_full + cs*8, cph);
            const __half* St  = smh + cs * STG_DN_H;
            const __half* As  = St;
            const __half* B1s = St + 5120;
            #pragma unroll
            for (int ks = 0; ks < 2; ks++) {
                FragA a[2];
                #pragma unroll
                for (int mi = 0; mi < 2; mi++)
                    wmma::load_matrix_sync(a[mi], As + (warpM*32 + mi*16) * LDA_H + ks*16, LDA_H);
                #pragma unroll
                for (int ni = 0; ni < 2; ni++) {
                    FragB b;
                    wmma::load_matrix_sync(b, B1s + (ks*16) * LDB_H + warpN*32 + ni*16, LDB_H);
                    #pragma unroll
                    for (int mi = 0; mi < 2; mi++)
                        wmma::mma_sync(c[mi][ni], a[mi], b, c[mi][ni]);
                }
            }
            __syncwarp();
            if (lane == 0) mbar_arrive(mb_empty + cs*8);
            if (++cs == NSTAGE) { cs = 0; cph ^= 1; }
        }
    }
    __syncthreads();

    float* Cs = (float*)smh;
    if (wid < 8) {
        #pragma unroll
        for (int mi = 0; mi < 2; mi++)
            #pragma unroll
            for (int ni = 0; ni < 2; ni++)
                wmma::store_matrix_sync(Cs + (warpM*32 + mi*16) * LDC + warpN*32 + ni*16,
                                        c[mi][ni], LDC, wmma::mem_row_major);
    }
    __syncthreads();

    int valid = cnt - row0; if (valid > 128) valid = 128;
    #pragma unroll
    for (int i = 0; i < 4; i++) {
        int lin = tid + i * 512;
        int row = lin >> 4, cc = lin & 15;
        if (row < valid) {
            float4 v = *(float4*)(Cs + row * LDC + cc * 4);
            *(float4*)(dstbuf + (size_t)(base + row0 + row) * D_DIM + d0 + cc * 4) = v;
        }
    }
}

// ---------------- combine (applies gate weights) ----------------
__global__ void combine_kernel(float* __restrict__ out) {
    int t = blockIdx.x;
    __shared__ int p[TOPK];
    __shared__ float w[TOPK];
    if (threadIdx.x < TOPK) {
        p[threadIdx.x] = g_tok_pair[t*TOPK + threadIdx.x];
        w[threadIdx.x] = g_tok_w[t*TOPK + threadIdx.x];
    }
    __syncthreads();
    int d = threadIdx.x * 4;
    float4 s = *(float4*)(out + (size_t)t * D_DIM + d);
    #pragma unroll
    for (int k = 0; k < TOPK; k++) {
        const float4 v = *(const float4*)(g_dbuf + (size_t)p[k] * D_DIM + d);
        float wk = w[k];
        s.x += wk*v.x; s.y += wk*v.y; s.z += wk*v.z; s.w += wk*v.w;
    }
    *(float4*)(out + (size_t)t * D_DIM + d) = s;
}

// ---------------------------------------------------------------------------
extern "C" void kernel_launch(void* const* d_in, const int* in_sizes, int n_in,
                              void* d_out, int out_size) {
    const float* x   = (const float*)d_in[0];
    const float* wg  = (const float*)d_in[1];
    const float* gb  = (const float*)d_in[2];
    const float* w1s = (const float*)d_in[3];
    const float* w2s = (const float*)d_in[4];
    const float* w3s = (const float*)d_in[5];
    const float* w1r = (const float*)d_in[6];
    const float* w2r = (const float*)d_in[7];
    const float* w3r = (const float*)d_in[8];
    float* out = (float*)d_out;

    float* scores;
    if (out_size >= NTOK*D_DIM + NTOK*E_NUM) {
        scores = out + (size_t)NTOK * D_DIM;
    } else {
        cudaGetSymbolAddress((void**)&scores, g_scores_scratch);
    }

    static int attr_done = 0;
    if (!attr_done) {
        cudaFuncSetAttribute(up_fused,   cudaFuncAttributeMaxDynamicSharedMemorySize, SMEM_UP_B);
        cudaFuncSetAttribute(down_fused, cudaFuncAttributeMaxDynamicSharedMemorySize, SMEM_DN_B);
        attr_done = 1;
    }

    init_kernel<<<1, 64>>>();
    gate_kernel<<<NTOK, 128>>>(x, wg, gb, scores);
    scan_assign_kernel<<<1, NTOK>>>();

    up_fused<<<dim3(FS_DIM/64, E_NUM + 1, 8), 512, SMEM_UP_B>>>(x, w1r, w3r, w1s, w3s);
    down_fused<<<dim3(D_DIM/64, E_NUM + 1, 8), 512, SMEM_DN_B>>>(w2r, w2s, out);

    combine_kernel<<<NTOK, 256>>>(out);
}